// round 11
// baseline (speedup 1.0000x reference)
#include <cuda_runtime.h>

#define Tn 512
#define Bn 64
#define Vn 256
#define Hn 512
#define GRID_SCAN 128
#define NTHR 256
#define RSTRIDE 37

// ---------------- device scratch (no allocations allowed) ----------------
__device__ float g_embhg[Vn * 2 * Hn];             // emb @ w_in[0] : [256][1024]
__device__ float g_state[2][2][Hn * Bn];           // [layer][parity][col*64 + b]
__device__ float g_l0f[2][Hn * Bn];                // L0-final handoff, by t&1
__device__ float g_hidden[(size_t)Tn * Bn * Hn];   // [t][b][col]
__device__ unsigned g_bar_count;
__device__ unsigned g_bar_gen;

// ---------------- grid-wide barrier (release/acquire) ----------------
__device__ __forceinline__ void grid_sync() {
  __syncthreads();
  if (threadIdx.x == 0) {
    unsigned gen;
    asm volatile("ld.relaxed.gpu.global.u32 %0, [%1];"
                 : "=r"(gen) : "l"(&g_bar_gen) : "memory");
    unsigned prev;
    asm volatile("atom.add.acq_rel.gpu.global.u32 %0, [%1], %2;"
                 : "=r"(prev) : "l"(&g_bar_count), "r"(1u) : "memory");
    if (prev == GRID_SCAN - 1u) {
      asm volatile("st.relaxed.gpu.global.u32 [%0], %1;"
                   :: "l"(&g_bar_count), "r"(0u) : "memory");
      asm volatile("st.release.gpu.global.u32 [%0], %1;"
                   :: "l"(&g_bar_gen), "r"(gen + 1u) : "memory");
    } else {
      unsigned cur;
      do {
        asm volatile("ld.acquire.gpu.global.u32 %0, [%1];"
                     : "=r"(cur) : "l"(&g_bar_gen) : "memory");
      } while (cur == gen);
    }
  }
  __syncthreads();
}

// ---------------- packed f32x2 helpers ----------------
__device__ __forceinline__ unsigned long long pack2(float v) {
  unsigned long long r;
  unsigned u = __float_as_uint(v);
  asm("mov.b64 %0, {%1, %1};" : "=l"(r) : "r"(u));
  return r;
}
__device__ __forceinline__ void fma2(unsigned long long& d,
                                     unsigned long long a,
                                     unsigned long long b) {
  asm("fma.rn.f32x2 %0, %1, %2, %0;" : "+l"(d) : "l"(a), "l"(b));
}

// one s scalar against 16 cols (8 packed FMA2)
#define FMA2ROW16(bi, sv)                                                    \
  {                                                                          \
    unsigned long long sd = pack2(sv);                                       \
    fma2(acc[bi][0], sd, w0.x); fma2(acc[bi][1], sd, w0.y);                  \
    fma2(acc[bi][2], sd, w1.x); fma2(acc[bi][3], sd, w1.y);                  \
    fma2(acc[bi][4], sd, w2.x); fma2(acc[bi][5], sd, w2.y);                  \
    fma2(acc[bi][6], sd, w3.x); fma2(acc[bi][7], sd, w3.y);                  \
  }

// ---------------- K=512 partial GEMM pass: 4 batches x 16 cols ----------
// Thread (ks, bg) accumulates over its 32 k values (k = ks + 16*i).
// s via coalesced LDG.128 from L2 (double-buffered, prefetched), weights via
// broadcast LDS.128 from resident SMEM rows [k][16] = [h0..h7, g0..g7].
__device__ __forceinline__ void kpass16(unsigned long long acc[4][8],
    const float* __restrict__ src, const float* __restrict__ wmat,
    int ks, int bg)
{
  const float4* srcv = (const float4*)src;   // [512][16] float4
  float4 sb[2][8];
#pragma unroll
  for (int j = 0; j < 8; ++j)
    sb[0][j] = __ldcg(srcv + (ks + 16 * j) * 16 + bg);
#pragma unroll
  for (int g = 0; g < 4; ++g) {
    if (g < 3) {
#pragma unroll
      for (int j = 0; j < 8; ++j)
        sb[(g + 1) & 1][j] =
            __ldcg(srcv + (ks + 16 * (8 * (g + 1) + j)) * 16 + bg);
    }
#pragma unroll
    for (int j = 0; j < 8; ++j) {
      int k = ks + 16 * (8 * g + j);
      const ulonglong2* wr = (const ulonglong2*)(wmat + k * 16);
      ulonglong2 w0 = wr[0], w1 = wr[1], w2 = wr[2], w3 = wr[3];
      float4 s4 = sb[g & 1][j];
      FMA2ROW16(0, s4.x)
      FMA2ROW16(1, s4.y)
      FMA2ROW16(2, s4.z)
      FMA2ROW16(3, s4.w)
    }
  }
}

// ---------------- kernel 1: embhg = emb @ w_in[0] ----------------
// 64 CTAs x 4 vocab rows; float4 weight reads; each CTA reads w_in once.
__global__ void __launch_bounds__(NTHR, 1) embhg_kernel(
    const float* __restrict__ emb, const float* __restrict__ w_in) {
  __shared__ float e_sm[4 * 512];
  int v0 = blockIdx.x * 4;
  for (int i = threadIdx.x; i < 4 * 512; i += NTHR)
    e_sm[i] = emb[v0 * 512 + i];
  __syncthreads();
  int j4 = threadIdx.x * 4;
  float4 acc[4];
#pragma unroll
  for (int v = 0; v < 4; ++v) acc[v] = make_float4(0.f, 0.f, 0.f, 0.f);
  for (int k = 0; k < 512; ++k) {
    float4 w = *(const float4*)(w_in + (size_t)k * 1024 + j4);
#pragma unroll
    for (int v = 0; v < 4; ++v) {
      float e = e_sm[v * 512 + k];
      acc[v].x = fmaf(e, w.x, acc[v].x);
      acc[v].y = fmaf(e, w.y, acc[v].y);
      acc[v].z = fmaf(e, w.z, acc[v].z);
      acc[v].w = fmaf(e, w.w, acc[v].w);
    }
  }
#pragma unroll
  for (int v = 0; v < 4; ++v)
    *(float4*)(g_embhg + (size_t)(v0 + v) * 1024 + j4) = acc[v];
}

// ---------------- kernel 2: layer-pipelined persistent scan ----------------
// CTAs 0..63  = layer 0, columns cta*8..+7, timestep t
// CTAs 64..127= layer 1, columns (cta-64)*8..+7, timestep t-1
// SMEM: ws [<=5][512][16] (cols h0..h7,g0..g7), bs [<=5][16],
//       red [256][37] (stride 37: conflict-free scalar STS/LDS both patterns)
__global__ void __launch_bounds__(NTHR, 1) scan_kernel(
    const int* __restrict__ x, const float* __restrict__ w_in,
    const float* __restrict__ w_h, const float* __restrict__ b_h,
    float* __restrict__ d_out)
{
  extern __shared__ float smem[];
  float* ws = smem;                  // up to 5*8192 floats
  float* bs = ws + 5 * 8192;         // 80 floats
  float* red = bs + 80;              // 256*37 floats

  const int tid = threadIdx.x;
  const int cta = blockIdx.x;
  const int group = cta >> 6;        // 0 = layer0, 1 = layer1
  const int cg = cta & 63;           // column-group within layer

  // --- weight slices -> SMEM, layout [m][k][16] ---
  const int nm = group ? 5 : 4;
  for (int idx = tid; idx < nm * 8192; idx += NTHR) {
    int m = idx >> 13;
    int r = idx & 8191;
    int k = r >> 4;
    int c = r & 15;
    int col = cg * 8 + (c & 7) + ((c >> 3) << 9);
    const float* W;
    if (group == 0)      W = w_h + (size_t)m * 512 * 1024;
    else if (m < 4)      W = w_h + (size_t)(4 + m) * 512 * 1024;
    else                 W = w_in + (size_t)512 * 1024;
    ws[idx] = W[(size_t)k * 1024 + col];
  }
  if (tid < 64) {
    int m = tid >> 4, c = tid & 15;
    int col = cg * 8 + (c & 7) + ((c >> 3) << 9);
    bs[tid] = b_h[(group * 4 + m) * 1024 + col];
  }
  for (int i = cta * NTHR + tid; i < 2 * 2 * Hn * Bn; i += GRID_SCAN * NTHR)
    ((float*)g_state)[i] = 0.f;
  grid_sync();

  const int ks = tid >> 4;          // k-slice 0..15
  const int bg = tid & 15;          // batch group (4 batches)
  const int c0 = tid >> 6;          // combine role: column 0..3 (also c0+4)
  const int bq = tid & 63;          // combine role: batch 0..63
  const int redoff = (bq >> 2) * RSTRIDE + (bq & 3) * 8;
  const int colA = cg * 8 + c0;     // global h-columns handled in combine
  const int colB = colA + 4;
  float* myred = red + tid * RSTRIDE;
  float* mystate = (float*)g_state[group];
  int par = 0;

#pragma unroll 1
  for (int t = 0; t <= Tn; ++t) {
    const bool act = group == 0 ? (t < Tn) : (t >= 1);
    const int te = group == 0 ? t : t - 1;   // effective timestep

    // hoisted per-timestep operands (layer 0 d0 input projection)
    float ehA = 0.f, ehB = 0.f, egA = 0.f, egB = 0.f;
    if (group == 0 && act) {
      int tk = x[t * Bn + bq];
      ehA = g_embhg[tk * 1024 + colA];
      ehB = g_embhg[tk * 1024 + colB];
      egA = g_embhg[tk * 1024 + 512 + colA];
      egB = g_embhg[tk * 1024 + 512 + colB];
    }

#pragma unroll 1
    for (int d = 0; d < 4; ++d) {
      if (act) {
        const float* src = mystate + par * (Hn * Bn);
        float sA = __ldcg(src + colA * 64 + bq);   // early issue
        float sB = __ldcg(src + colB * 64 + bq);

        unsigned long long acc[4][8];
#pragma unroll
        for (int a = 0; a < 4; ++a)
#pragma unroll
          for (int c = 0; c < 8; ++c) acc[a][c] = 0ull;

        kpass16(acc, src, ws + d * 8192, ks, bg);
        if (group == 1 && d == 0)
          kpass16(acc, g_l0f[te & 1], ws + 4 * 8192, ks, bg);

        // ---- combine, phase H ----
#pragma unroll
        for (int a = 0; a < 4; ++a)
#pragma unroll
          for (int c = 0; c < 4; ++c) {
            unsigned lo, hi;
            asm("mov.b64 {%0, %1}, %2;" : "=r"(lo), "=r"(hi) : "l"(acc[a][c]));
            myred[a * 8 + 2 * c] = __uint_as_float(lo);
            myred[a * 8 + 2 * c + 1] = __uint_as_float(hi);
          }
        __syncthreads();
        float hsA = bs[d * 16 + c0];
        float hsB = bs[d * 16 + c0 + 4];
#pragma unroll
        for (int k2 = 0; k2 < 16; ++k2) {
          const float* rr = red + k2 * 16 * RSTRIDE + redoff;
          hsA += rr[c0];
          hsB += rr[c0 + 4];
        }
        __syncthreads();

        // ---- combine, phase G ----
#pragma unroll
        for (int a = 0; a < 4; ++a)
#pragma unroll
          for (int c = 0; c < 4; ++c) {
            unsigned lo, hi;
            asm("mov.b64 {%0, %1}, %2;" : "=r"(lo), "=r"(hi) : "l"(acc[a][4 + c]));
            myred[a * 8 + 2 * c] = __uint_as_float(lo);
            myred[a * 8 + 2 * c + 1] = __uint_as_float(hi);
          }
        __syncthreads();
        float gsA = bs[d * 16 + 8 + c0];
        float gsB = bs[d * 16 + 12 + c0];
#pragma unroll
        for (int k2 = 0; k2 < 16; ++k2) {
          const float* rr = red + k2 * 16 * RSTRIDE + redoff;
          gsA += rr[c0];
          gsB += rr[c0 + 4];
        }
        if (group == 0 && d == 0) {
          hsA += ehA; hsB += ehB; gsA += egA; gsB += egB;
        }
        float hhA = tanhf(hsA), hhB = tanhf(hsB);
        float ggA = 1.f / (1.f + __expf(-gsA));
        float ggB = 1.f / (1.f + __expf(-gsB));
        float snA = fmaf(ggA, hhA - sA, sA);
        float snB = fmaf(ggB, hhB - sB, sB);
        float* dst = mystate + (par ^ 1) * (Hn * Bn);
        __stcg(dst + colA * 64 + bq, snA);
        __stcg(dst + colB * 64 + bq, snB);
        if (d == 3) {
          if (group == 0) {
            __stcg(g_l0f[t & 1] + colA * 64 + bq, snA);
            __stcg(g_l0f[t & 1] + colB * 64 + bq, snB);
          } else {
            g_hidden[((size_t)te * Bn + bq) * 512 + colA] = snA;
            g_hidden[((size_t)te * Bn + bq) * 512 + colB] = snB;
          }
        }
        par ^= 1;
      }
      grid_sync();
    }
  }

  // ---- s_final: [L][B][H] appended after the logits block ----
  const size_t SFIN = (size_t)Tn * Bn * Vn;
  const float* fin = mystate + par * (Hn * Bn);
  d_out[SFIN + (size_t)group * (Bn * Hn) + bq * 512 + colA] =
      __ldcg(fin + colA * 64 + bq);
  d_out[SFIN + (size_t)group * (Bn * Hn) + bq * 512 + colB] =
      __ldcg(fin + colB * 64 + bq);
}

// ---------------- kernel 3: logits = hidden @ w_fc + b_fc ----------------
__global__ void __launch_bounds__(NTHR, 1) logits_kernel(
    const float* __restrict__ w_fc, const float* __restrict__ b_fc,
    float* __restrict__ out)
{
  extern __shared__ float a_sm[];  // [64][512]
  int tid = threadIdx.x;
  size_t row0 = (size_t)blockIdx.x * 64;
  for (int i = tid; i < 64 * 512 / 4; i += NTHR)
    ((float4*)a_sm)[i] = ((const float4*)(g_hidden + row0 * 512))[i];
  __syncthreads();

  float acc[64];
#pragma unroll
  for (int r = 0; r < 64; ++r) acc[r] = 0.f;

#pragma unroll 2
  for (int k = 0; k < 512; k += 4) {
    float w0 = w_fc[(size_t)(k + 0) * 256 + tid];
    float w1 = w_fc[(size_t)(k + 1) * 256 + tid];
    float w2 = w_fc[(size_t)(k + 2) * 256 + tid];
    float w3 = w_fc[(size_t)(k + 3) * 256 + tid];
#pragma unroll
    for (int r = 0; r < 64; ++r) {
      float4 a = *(const float4*)(a_sm + r * 512 + k);
      acc[r] = fmaf(a.x, w0, acc[r]);
      acc[r] = fmaf(a.y, w1, acc[r]);
      acc[r] = fmaf(a.z, w2, acc[r]);
      acc[r] = fmaf(a.w, w3, acc[r]);
    }
  }
  float bias = b_fc[tid];
#pragma unroll
  for (int r = 0; r < 64; ++r)
    out[(row0 + r) * 256 + tid] = acc[r] + bias;
}

// ---------------- launch ----------------
extern "C" void kernel_launch(void* const* d_in, const int* in_sizes, int n_in,
                              void* d_out, int out_size) {
  const int*   x    = (const int*)d_in[0];    // [512,64] int32
  const float* emb  = (const float*)d_in[1];  // [256,512]
  const float* w_in = (const float*)d_in[2];  // [2,512,1024]
  const float* w_h  = (const float*)d_in[3];  // [2,4,512,1024]
  const float* b_h  = (const float*)d_in[4];  // [2,4,1024]
  const float* w_fc = (const float*)d_in[5];  // [512,256]
  const float* b_fc = (const float*)d_in[6];  // [256]
  float* out = (float*)d_out;

  const int SCAN_SMEM = (5 * 8192 + 80 + 256 * RSTRIDE) * 4;
  const int LOGITS_SMEM = 64 * 512 * 4;
  cudaFuncSetAttribute(scan_kernel,
                       cudaFuncAttributeMaxDynamicSharedMemorySize, SCAN_SMEM);
  cudaFuncSetAttribute(logits_kernel,
                       cudaFuncAttributeMaxDynamicSharedMemorySize, LOGITS_SMEM);

  embhg_kernel<<<64, NTHR>>>(emb, w_in);
  scan_kernel<<<GRID_SCAN, NTHR, SCAN_SMEM>>>(x, w_in, w_h, b_h, out);
  logits_kernel<<<(Tn * Bn) / 64, NTHR, LOGITS_SMEM>>>(w_fc, b_fc, out);
}

// round 13
// speedup vs baseline: 1.0038x; 1.0038x over previous
#include <cuda_runtime.h>

#define Tn 512
#define Bn 64
#define Vn 256
#define Hn 512
#define GRID_SCAN 128
#define NTHR 256
#define RSTRIDE 38
#define PADU 32

// ---------------- device scratch (no allocations allowed) ----------------
__device__ float g_embhg[Vn * 2 * Hn];             // emb @ w_in[0] : [256][1024]
__device__ float g_state[2][2][Hn * Bn];           // [layer][parity][col*64 + b]
__device__ float g_l0f[2][Hn * Bn];                // L0-final handoff, by t&1
__device__ float g_hidden[(size_t)Tn * Bn * Hn];   // [t][b][col]
__device__ unsigned g_bar_count;
__device__ unsigned g_bar_gen;
__device__ unsigned g_flags[2][64 * PADU];         // per-CTA phase-completion flags

// ---------------- one-time grid barrier (init only) ----------------
__device__ __forceinline__ void grid_sync() {
  __syncthreads();
  if (threadIdx.x == 0) {
    unsigned gen;
    asm volatile("ld.relaxed.gpu.global.u32 %0, [%1];"
                 : "=r"(gen) : "l"(&g_bar_gen) : "memory");
    unsigned prev;
    asm volatile("atom.add.acq_rel.gpu.global.u32 %0, [%1], %2;"
                 : "=r"(prev) : "l"(&g_bar_count), "r"(1u) : "memory");
    if (prev == GRID_SCAN - 1u) {
      asm volatile("st.relaxed.gpu.global.u32 [%0], %1;"
                   :: "l"(&g_bar_count), "r"(0u) : "memory");
      asm volatile("st.release.gpu.global.u32 [%0], %1;"
                   :: "l"(&g_bar_gen), "r"(gen + 1u) : "memory");
    } else {
      unsigned cur;
      do {
        asm volatile("ld.acquire.gpu.global.u32 %0, [%1];"
                     : "=r"(cur) : "l"(&g_bar_gen) : "memory");
      } while (cur == gen);
    }
  }
  __syncthreads();
}

// ---------------- flag / gate primitives ----------------
__device__ __forceinline__ unsigned ld_acq_gpu(const unsigned* p) {
  unsigned v;
  asm volatile("ld.acquire.gpu.global.u32 %0, [%1];" : "=r"(v) : "l"(p) : "memory");
  return v;
}
__device__ __forceinline__ void st_rel_gpu(unsigned* p, unsigned v) {
  asm volatile("st.release.gpu.global.u32 [%0], %1;" :: "l"(p), "r"(v) : "memory");
}
__device__ __forceinline__ void cnt_add(unsigned saddr) {
  asm volatile("red.release.cta.shared.add.u32 [%0], %1;" :: "r"(saddr), "r"(1u) : "memory");
}
__device__ __forceinline__ void gate16(unsigned saddr) {
  unsigned v;
  do {
    asm volatile("ld.acquire.cta.shared.u32 %0, [%1];" : "=r"(v) : "r"(saddr) : "memory");
  } while (v < 16u);
}
__device__ __forceinline__ void pollflag(const unsigned* f, unsigned target,
                                         unsigned cnt_saddr) {
  unsigned v;
  do { v = ld_acq_gpu(f); } while ((int)(v - target) < 0);
  cnt_add(cnt_saddr);
}

// ---------------- packed f32x2 helpers ----------------
__device__ __forceinline__ unsigned long long pack2(float v) {
  unsigned long long r;
  unsigned u = __float_as_uint(v);
  asm("mov.b64 %0, {%1, %1};" : "=l"(r) : "r"(u));
  return r;
}
__device__ __forceinline__ void fma2(unsigned long long& d,
                                     unsigned long long a,
                                     unsigned long long b) {
  asm("fma.rn.f32x2 %0, %1, %2, %0;" : "+l"(d) : "l"(a), "l"(b));
}

#define FMA2ROW16(bi, sv)                                                    \
  {                                                                          \
    unsigned long long sd = pack2(sv);                                       \
    fma2(acc[bi][0], sd, w0.x); fma2(acc[bi][1], sd, w0.y);                  \
    fma2(acc[bi][2], sd, w1.x); fma2(acc[bi][3], sd, w1.y);                  \
    fma2(acc[bi][4], sd, w2.x); fma2(acc[bi][5], sd, w2.y);                  \
    fma2(acc[bi][6], sd, w3.x); fma2(acc[bi][7], sd, w3.y);                  \
  }

// ---------------- K=512 partial GEMM pass, stage-gated ----------------
// Group g (k in [128g,128g+128)) is gated on cnt[stage g] == 16, i.e. the 16
// producer CTAs of those columns have released this phase.
__device__ __forceinline__ void kpass16(unsigned long long acc[4][8],
    const float* __restrict__ src, const float* __restrict__ wmat,
    int ks, int bg, unsigned cnt_saddr)
{
  const float4* srcv = (const float4*)src;   // [512][16] float4
  float4 sb[2][8];
  gate16(cnt_saddr);
#pragma unroll
  for (int j = 0; j < 8; ++j)
    sb[0][j] = __ldcg(srcv + (ks + 16 * j) * 16 + bg);
#pragma unroll
  for (int g = 0; g < 4; ++g) {
    if (g < 3) {
      gate16(cnt_saddr + 4u * (unsigned)(g + 1));
#pragma unroll
      for (int j = 0; j < 8; ++j)
        sb[(g + 1) & 1][j] =
            __ldcg(srcv + (ks + 16 * (8 * (g + 1) + j)) * 16 + bg);
    }
#pragma unroll
    for (int j = 0; j < 8; ++j) {
      int k = ks + 16 * (8 * g + j);
      const ulonglong2* wr = (const ulonglong2*)(wmat + k * 16);
      ulonglong2 w0 = wr[0], w1 = wr[1], w2 = wr[2], w3 = wr[3];
      float4 s4 = sb[g & 1][j];
      FMA2ROW16(0, s4.x)
      FMA2ROW16(1, s4.y)
      FMA2ROW16(2, s4.z)
      FMA2ROW16(3, s4.w)
    }
  }
}

// ---------------- kernel 1: embhg = emb @ w_in[0] ----------------
__global__ void __launch_bounds__(NTHR, 1) embhg_kernel(
    const float* __restrict__ emb, const float* __restrict__ w_in) {
  __shared__ float e_sm[4 * 512];
  int v0 = blockIdx.x * 4;
  for (int i = threadIdx.x; i < 4 * 512; i += NTHR)
    e_sm[i] = emb[v0 * 512 + i];
  __syncthreads();
  int j4 = threadIdx.x * 4;
  float4 acc[4];
#pragma unroll
  for (int v = 0; v < 4; ++v) acc[v] = make_float4(0.f, 0.f, 0.f, 0.f);
  for (int k = 0; k < 512; ++k) {
    float4 w = *(const float4*)(w_in + (size_t)k * 1024 + j4);
#pragma unroll
    for (int v = 0; v < 4; ++v) {
      float e = e_sm[v * 512 + k];
      acc[v].x = fmaf(e, w.x, acc[v].x);
      acc[v].y = fmaf(e, w.y, acc[v].y);
      acc[v].z = fmaf(e, w.z, acc[v].z);
      acc[v].w = fmaf(e, w.w, acc[v].w);
    }
  }
#pragma unroll
  for (int v = 0; v < 4; ++v)
    *(float4*)(g_embhg + (size_t)(v0 + v) * 1024 + j4) = acc[v];
}

// ---------------- kernel 2: flag-synced layer-pipelined scan ----------------
__global__ void __launch_bounds__(NTHR, 1) scan_kernel(
    const int* __restrict__ x, const float* __restrict__ w_in,
    const float* __restrict__ w_h, const float* __restrict__ b_h,
    float* __restrict__ d_out)
{
  extern __shared__ float smem[];
  float* ws = smem;                  // up to 5*8192 floats
  float* bs = ws + 5 * 8192;         // 80 floats
  float* red = bs + 80;              // 256*38 floats
  __shared__ int cnt[16];            // [grp(0=own,1=oth)][parity][stage]
  const unsigned cnt_base = (unsigned)__cvta_generic_to_shared(cnt);

  const int tid = threadIdx.x;
  const int cta = blockIdx.x;
  const int group = cta >> 6;        // 0 = layer0, 1 = layer1
  const int cg = cta & 63;           // column-group within layer

  // --- weight slices -> SMEM, layout [m][k][16] (h0..h7, g0..g7) ---
  const int nm = group ? 5 : 4;
  for (int idx = tid; idx < nm * 8192; idx += NTHR) {
    int m = idx >> 13;
    int r = idx & 8191;
    int k = r >> 4;
    int c = r & 15;
    int col = cg * 8 + (c & 7) + ((c >> 3) << 9);
    const float* W;
    if (group == 0)      W = w_h + (size_t)m * 512 * 1024;
    else if (m < 4)      W = w_h + (size_t)(4 + m) * 512 * 1024;
    else                 W = w_in + (size_t)512 * 1024;
    ws[idx] = W[(size_t)k * 1024 + col];
  }
  if (tid < 64) {
    int m = tid >> 4, c = tid & 15;
    int col = cg * 8 + (c & 7) + ((c >> 3) << 9);
    bs[tid] = b_h[(group * 4 + m) * 1024 + col];
  }
  for (int i = cta * NTHR + tid; i < 2 * 2 * Hn * Bn; i += GRID_SCAN * NTHR)
    ((float*)g_state)[i] = 0.f;
  if (tid == 0) g_flags[group][cg * PADU] = 0u;   // replay-safe reset
  if (tid < 16) cnt[tid] = 0;
  grid_sync();   // everyone's zeroing visible before any flag use

  const int ks = tid >> 4;           // k-slice 0..15
  const int bg = tid & 15;           // batch group (4 batches)
  const int c0 = tid >> 6;           // combine role: adjacent col pair index
  const int bq = tid & 63;           // combine role: batch 0..63
  const int bgq = bq >> 2;
  const int jq  = bq & 3;
  const int colA = cg * 8 + 2 * c0;  // adjacent global cols colA, colA+1
  float* myred = red + tid * RSTRIDE;
  float* mystate = (float*)g_state[group];
  unsigned* myflag = g_flags[group] + cg * PADU;
  int par = 0;

#pragma unroll 1
  for (int t = 0; t <= Tn; ++t) {
    const bool act = group == 0 ? (t < Tn) : (t >= 1);
    const int te = group == 0 ? t : t - 1;   // effective timestep

    float2 eh2 = make_float2(0.f, 0.f), eg2 = make_float2(0.f, 0.f);
    if (group == 0 && act) {
      int tk = x[t * Bn + bq];
      eh2 = *(const float2*)(g_embhg + tk * 1024 + colA);
      eg2 = *(const float2*)(g_embhg + tk * 1024 + 512 + colA);
    }

#pragma unroll 1
    for (int d = 0; d < 4; ++d) {
      const unsigned P_prev = (unsigned)(t * 4 + d);
      const int q = (int)(P_prev & 1u);
      const unsigned own_base = cnt_base + (unsigned)(q * 4) * 4u;
      const unsigned oth_base = cnt_base + (unsigned)(8 + q * 4) * 4u;

      if (act) {
        const float* src = mystate + par * (Hn * Bn);
        float sA = __ldcg(src + colA * 64 + bq);        // own cols: no gate
        float sB = __ldcg(src + (colA + 1) * 64 + bq);

        // ---- pollers: translate global flags into SMEM stage counters ----
        if (tid < 64) {
          pollflag(g_flags[group] + tid * PADU, P_prev,
                   own_base + (unsigned)(tid >> 4) * 4u);
        } else if (tid < 128) {
          int i = tid - 64;
          if (group == 1) {
            if (d == 0)
              pollflag(g_flags[0] + i * PADU, (unsigned)(4 * t),
                       oth_base + (unsigned)(i >> 4) * 4u);
          } else {
            if (d == 3 && t >= 2)
              pollflag(g_flags[1] + i * PADU, (unsigned)(4 * t - 3),
                       oth_base + (unsigned)(i >> 4) * 4u);
          }
        }

        unsigned long long acc[4][8];
#pragma unroll
        for (int a = 0; a < 4; ++a)
#pragma unroll
          for (int c = 0; c < 8; ++c) acc[a][c] = 0ull;

        kpass16(acc, src, ws + d * 8192, ks, bg, own_base);
        if (group == 1 && d == 0)
          kpass16(acc, g_l0f[te & 1], ws + 4 * 8192, ks, bg, oth_base);

        // ---- combine, phase H (packed u64 stores, float2 reads) ----
#pragma unroll
        for (int a = 0; a < 4; ++a)
#pragma unroll
          for (int c = 0; c < 4; ++c)
            *(unsigned long long*)(myred + a * 8 + 2 * c) = acc[a][c];
        __syncthreads();
        float hsA = bs[d * 16 + 2 * c0];
        float hsB = bs[d * 16 + 2 * c0 + 1];
#pragma unroll
        for (int k2 = 0; k2 < 16; ++k2) {
          float2 hv = *(const float2*)(red + (k2 * 16 + bgq) * RSTRIDE +
                                       jq * 8 + 2 * c0);
          hsA += hv.x; hsB += hv.y;
        }
        __syncthreads();

        // ---- combine, phase G ----
#pragma unroll
        for (int a = 0; a < 4; ++a)
#pragma unroll
          for (int c = 0; c < 4; ++c)
            *(unsigned long long*)(myred + a * 8 + 2 * c) = acc[a][4 + c];
        __syncthreads();
        float gsA = bs[d * 16 + 8 + 2 * c0];
        float gsB = bs[d * 16 + 8 + 2 * c0 + 1];
#pragma unroll
        for (int k2 = 0; k2 < 16; ++k2) {
          float2 gv = *(const float2*)(red + (k2 * 16 + bgq) * RSTRIDE +
                                       jq * 8 + 2 * c0);
          gsA += gv.x; gsB += gv.y;
        }
        if (group == 0 && d == 0) {
          hsA += eh2.x; hsB += eh2.y; gsA += eg2.x; gsB += eg2.y;
        }
        float hhA = tanhf(hsA), hhB = tanhf(hsB);
        float ggA = 1.f / (1.f + __expf(-gsA));
        float ggB = 1.f / (1.f + __expf(-gsB));
        float snA = fmaf(ggA, hhA - sA, sA);
        float snB = fmaf(ggB, hhB - sB, sB);
        float* dst = mystate + (par ^ 1) * (Hn * Bn);
        __stcg(dst + colA * 64 + bq, snA);
        __stcg(dst + (colA + 1) * 64 + bq, snB);
        if (d == 3) {
          if (group == 0) {
            if (t >= 2) {   // l0f[t&1] reader (L1 work t-2, d0) must be done
              gate16(oth_base);
              gate16(oth_base + 4u);
              gate16(oth_base + 8u);
              gate16(oth_base + 12u);
            }
            __stcg(g_l0f[t & 1] + colA * 64 + bq, snA);
            __stcg(g_l0f[t & 1] + (colA + 1) * 64 + bq, snB);
          } else {
            *(float2*)(g_hidden + ((size_t)te * Bn + bq) * 512 + colA) =
                make_float2(snA, snB);
          }
        }
        par ^= 1;
      }

      __syncthreads();                       // all stores done
      if (tid == 0) st_rel_gpu(myflag, P_prev + 1u);
      if (tid < 8)                            // reset other parity's counters
        cnt[(tid >> 2) * 8 + (q ^ 1) * 4 + (tid & 3)] = 0;
      __syncthreads();                       // resets visible next phase
    }
  }

  // ---- s_final: [L][B][H] appended after the logits block ----
  const size_t SFIN = (size_t)Tn * Bn * Vn;
  const float* fin = mystate + par * (Hn * Bn);
  float fA = __ldcg(fin + colA * 64 + bq);
  float fB = __ldcg(fin + (colA + 1) * 64 + bq);
  *(float2*)(d_out + SFIN + (size_t)group * (Bn * Hn) + bq * 512 + colA) =
      make_float2(fA, fB);
}

// ---------------- kernel 3: logits = hidden @ w_fc + b_fc ----------------
__global__ void __launch_bounds__(NTHR, 1) logits_kernel(
    const float* __restrict__ w_fc, const float* __restrict__ b_fc,
    float* __restrict__ out)
{
  extern __shared__ float a_sm[];  // [64][512]
  int tid = threadIdx.x;
  size_t row0 = (size_t)blockIdx.x * 64;
  for (int i = tid; i < 64 * 512 / 4; i += NTHR)
    ((float4*)a_sm)[i] = ((const float4*)(g_hidden + row0 * 512))[i];
  __syncthreads();

  float acc[64];
#pragma unroll
  for (int r = 0; r < 64; ++r) acc[r] = 0.f;

#pragma unroll 2
  for (int k = 0; k < 512; k += 4) {
    float w0 = w_fc[(size_t)(k + 0) * 256 + tid];
    float w1 = w_fc[(size_t)(k + 1) * 256 + tid];
    float w2 = w_fc[(size_t)(k + 2) * 256 + tid];
    float w3 = w_fc[(size_t)(k + 3) * 256 + tid];
#pragma unroll
    for (int r = 0; r < 64; ++r) {
      float4 a = *(const float4*)(a_sm + r * 512 + k);
      acc[r] = fmaf(a.x, w0, acc[r]);
      acc[r] = fmaf(a.y, w1, acc[r]);
      acc[r] = fmaf(a.z, w2, acc[r]);
      acc[r] = fmaf(a.w, w3, acc[r]);
    }
  }
  float bias = b_fc[tid];
#pragma unroll
  for (int r = 0; r < 64; ++r)
    out[(row0 + r) * 256 + tid] = acc[r] + bias;
}

// ---------------- launch ----------------
extern "C" void kernel_launch(void* const* d_in, const int* in_sizes, int n_in,
                              void* d_out, int out_size) {
  const int*   x    = (const int*)d_in[0];    // [512,64] int32
  const float* emb  = (const float*)d_in[1];  // [256,512]
  const float* w_in = (const float*)d_in[2];  // [2,512,1024]
  const float* w_h  = (const float*)d_in[3];  // [2,4,512,1024]
  const float* b_h  = (const float*)d_in[4];  // [2,4,1024]
  const float* w_fc = (const float*)d_in[5];  // [512,256]
  const float* b_fc = (const float*)d_in[6];  // [256]
  float* out = (float*)d_out;

  const int SCAN_SMEM = (5 * 8192 + 80 + 256 * RSTRIDE) * 4;
  const int LOGITS_SMEM = 64 * 512 * 4;
  cudaFuncSetAttribute(scan_kernel,
                       cudaFuncAttributeMaxDynamicSharedMemorySize, SCAN_SMEM);
  cudaFuncSetAttribute(logits_kernel,
                       cudaFuncAttributeMaxDynamicSharedMemorySize, LOGITS_SMEM);

  embhg_kernel<<<64, NTHR>>>(emb, w_in);
  scan_kernel<<<GRID_SCAN, NTHR, SCAN_SMEM>>>(x, w_in, w_h, b_h, out);
  logits_kernel<<<(Tn * Bn) / 64, NTHR, LOGITS_SMEM>>>(w_fc, b_fc, out);
}